// round 9
// baseline (speedup 1.0000x reference)
#include <cuda_runtime.h>
#include <cuda_bf16.h>

#define HIMG 240
#define WIMG 135
#define HW   (HIMG * WIMG)
#define NF   1000
#define NV   600
#define INV_SIGMA 1.0e4f
#define BLURF 9.210240366975849e-4f
#define BAND  0.05f

#define NT     256                 // 8 warps
#define SPLIT  4                   // row-slices per face
#define NRAST  (NF * SPLIT)        // 4000 raster blocks
#define NFIN   127                 // finalize blocks: 127*256 = 32512 >= HW
#define NBLK   (NRAST + NFIN)

struct __align__(16) FD {
    float ax, ay, bx, by, cx, cy;
    float e0x, e0y, e1x, e1y, e2x, e2y;
    float rl0, rl1, rl2, rd0, rd1, rd2;
    int x0, x1, y0, y1;
    int skip;
};

__device__ float    g_sum[HW];    // zero at load; finalize self-cleans
__device__ float    g_flag[HW];   // zero at load; finalize self-cleans
__device__ unsigned g_done = 0;   // raster completions; reset by last fin block
__device__ unsigned g_fin  = 0;   // finalize blocks past the gate; self-resets

__global__ void __launch_bounds__(NT)
silhouette_kernel(const float* __restrict__ verts,
                  const int*   __restrict__ faces,
                  const float* __restrict__ gt,
                  float* __restrict__ out /* [0]=loss, [1..]=sil */) {
    const int tid  = threadIdx.x;
    const int lane = tid & 31;
    const int warp = tid >> 5;                  // 0..7
    const int bid  = blockIdx.x;

    // ======================= RASTER ROLE ==================================
    if (bid < NRAST) {
        __shared__ FD sfd;
        const int f  = bid >> 2;                // SPLIT == 4
        const int sl = bid & 3;

        if (bid == 0 && tid == 0) out[0] = 0.0f;

        // ---- setup: warp 0 only, broadcast via smem ----
        if (warp == 0) {
            int idx[3];
            idx[0] = faces[3 * f + 0];
            idx[1] = faces[3 * f + 1];
            idx[2] = faces[3 * f + 2];

            float Px[3], Py[3], zs[3];
#pragma unroll
            for (int k = 0; k < 3; k++) {
                float x = verts[3 * idx[k] + 0];
                float y = verts[3 * idx[k] + 1];
                float z = verts[3 * idx[k] + 2];
                float vx = -x, vy = -y, vz = z;     // R = diag(-1,-1,1)
                zs[k] = vz;
                float zz = fmaxf(vz, 1e-6f);
                Px[k] = (__fdividef(1000.0f * vx, zz) + 512.0f) * ((float)WIMG / 1024.0f);
                Py[k] = (__fdividef(1000.0f * vy, zz) + 512.0f) * ((float)HIMG / 1024.0f);
            }
            float tz = (zs[0] + zs[1] + zs[2]) * (1.0f / 3.0f);

            FD fd;
            fd.ax = Px[0]; fd.ay = Py[0];
            fd.bx = Px[1]; fd.by = Py[1];
            fd.cx = Px[2]; fd.cy = Py[2];
            fd.e0x = fd.bx - fd.ax; fd.e0y = fd.by - fd.ay;
            fd.e1x = fd.cx - fd.bx; fd.e1y = fd.cy - fd.by;
            fd.e2x = fd.ax - fd.cx; fd.e2y = fd.ay - fd.cy;
            float l0 = fd.e0x * fd.e0x + fd.e0y * fd.e0y + 1e-12f;
            float l1 = fd.e1x * fd.e1x + fd.e1y * fd.e1y + 1e-12f;
            float l2 = fd.e2x * fd.e2x + fd.e2y * fd.e2y + 1e-12f;
            fd.rl0 = rsqrtf(l0); fd.rl1 = rsqrtf(l1); fd.rl2 = rsqrtf(l2);
            fd.rd0 = fd.rl0 * fd.rl0;
            fd.rd1 = fd.rl1 * fd.rl1;
            fd.rd2 = fd.rl2 * fd.rl2;

            fd.skip = !(tz > 1e-6f);
            if (!fd.skip) {
                float minx = fminf(fd.ax, fminf(fd.bx, fd.cx));
                float maxx = fmaxf(fd.ax, fmaxf(fd.bx, fd.cx));
                float miny = fminf(fd.ay, fminf(fd.by, fd.cy));
                float maxy = fmaxf(fd.ay, fmaxf(fd.by, fd.cy));
                fd.x0 = max(0, (int)floorf(minx) - 1);
                fd.x1 = min(WIMG - 1, (int)ceilf(maxx));
                fd.y0 = max(0, (int)floorf(miny) - 1);
                fd.y1 = min(HIMG - 1, (int)ceilf(maxy));
                // point-degenerate: reference marks every pixel inside
                if (fd.e0x == 0.0f && fd.e0y == 0.0f &&
                    fd.e1x == 0.0f && fd.e1y == 0.0f) {
                    fd.x0 = 0; fd.x1 = WIMG - 1; fd.y0 = 0; fd.y1 = HIMG - 1;
                }
            } else {
                fd.x0 = 1; fd.x1 = 0; fd.y0 = 1; fd.y1 = 0;
            }
            if (lane == 0) sfd = fd;
        }
        __syncthreads();
        const FD fd = sfd;

        if (!fd.skip) {
            const int nrows = fd.y1 - fd.y0 + 1;
            for (int r = sl + warp * SPLIT; r < nrows; r += 8 * SPLIT) {
                int   iy  = fd.y0 + r;
                float py  = (float)iy + 0.5f;
                int   row = iy * WIMG;
                for (int ix = fd.x0 + lane; ix <= fd.x1; ix += 32) {
                    float px = (float)ix + 0.5f;

                    float apx0 = px - fd.ax, apy0 = py - fd.ay;
                    float apx1 = px - fd.bx, apy1 = py - fd.by;
                    float apx2 = px - fd.cx, apy2 = py - fd.cy;

                    float c0 = fd.e0x * apy0 - fd.e0y * apx0;
                    float c1 = fd.e1x * apy1 - fd.e1y * apx1;
                    float c2 = fd.e2x * apy2 - fd.e2y * apx2;
                    bool inside = (c0 >= 0.0f && c1 >= 0.0f && c2 >= 0.0f) ||
                                  (c0 <= 0.0f && c1 <= 0.0f && c2 <= 0.0f);

                    float dl = fminf(fabsf(c0) * fd.rl0,
                               fminf(fabsf(c1) * fd.rl1, fabsf(c2) * fd.rl2));

                    if (inside && dl > BAND) {
                        // log contribution <= -25: alpha saturates -> flag
                        g_flag[row + ix] = 1.0f;        // idempotent store
                    } else if (inside || dl <= BAND) {
                        float t0 = fminf(fmaxf((apx0 * fd.e0x + apy0 * fd.e0y) * fd.rd0, 0.0f), 1.0f);
                        float rx = apx0 - t0 * fd.e0x;
                        float ry = apy0 - t0 * fd.e0y;
                        float d2min = rx * rx + ry * ry;

                        float t1 = fminf(fmaxf((apx1 * fd.e1x + apy1 * fd.e1y) * fd.rd1, 0.0f), 1.0f);
                        rx = apx1 - t1 * fd.e1x;
                        ry = apy1 - t1 * fd.e1y;
                        d2min = fminf(d2min, rx * rx + ry * ry);

                        float t2 = fminf(fmaxf((apx2 * fd.e2x + apy2 * fd.e2y) * fd.rd2, 0.0f), 1.0f);
                        rx = apx2 - t2 * fd.e2x;
                        ry = apy2 - t2 * fd.e2y;
                        d2min = fminf(d2min, rx * rx + ry * ry);

                        if (inside || d2min <= BLURF) {
                            float u = (inside ? d2min : -d2min) * INV_SIGMA;
                            // log1p(-sigmoid(u)) == -softplus(u)
                            float sp = (u > 15.0f) ? u : log1pf(__expf(u));
                            if (sp != 0.0f) atomicAdd(&g_sum[row + ix], -sp);
                        }
                    }
                    // outside & dl > BAND -> d2 > BLURF -> reference-invalid
                }
            }
        }

        // signal completion (skipped faces too)
        __syncthreads();
        __threadfence();
        if (tid == 0) atomicAdd(&g_done, 1u);
        return;
    }

    // ======================= FINALIZE ROLE ================================
    {
        const int fb = bid - NRAST;               // 0..NFIN-1

        // gate: wait for all raster blocks (backoff spin, low L2 pressure)
        if (tid == 0) {
            while (atomicAdd(&g_done, 0u) < (unsigned)NRAST)
                __nanosleep(64);
        }
        __syncthreads();
        __threadfence();                           // acquire raster writes

        int i = fb * NT + tid;
        float local = 0.0f;
        if (i < HW) {
            float s  = g_sum[i];
            float fl = g_flag[i];
            g_sum[i]  = 0.0f;                      // self-clean for replay
            g_flag[i] = 0.0f;
            float alpha = (fl != 0.0f) ? 1.0f : (1.0f - expf(s));
            out[1 + i] = alpha;
            local = fabsf(alpha - gt[i]);
        }
#pragma unroll
        for (int o = 16; o > 0; o >>= 1)
            local += __shfl_down_sync(0xffffffffu, local, o);

        __shared__ float ws[8];
        if (lane == 0) ws[warp] = local;
        __syncthreads();
        if (warp == 0) {
            float v = (lane < 8) ? ws[lane] : 0.0f;
#pragma unroll
            for (int o = 4; o > 0; o >>= 1)
                v += __shfl_down_sync(0xffu, v, o);
            if (lane == 0)
                atomicAdd(out, v * (1.0f / (float)HW));
        }

        // counter hygiene for next graph replay: last finalize block past the
        // gate resets both counters. Every peer has already passed the gate
        // when g_fin reaches NFIN, so the reset cannot strand a spinner.
        if (tid == 0) {
            unsigned old = atomicAdd(&g_fin, 1u);
            if (old == NFIN - 1) {
                g_fin  = 0;
                g_done = 0;
                __threadfence();
            }
        }
    }
}

extern "C" void kernel_launch(void* const* d_in, const int* in_sizes, int n_in,
                              void* d_out, int out_size) {
    const float* verts = nullptr;
    const float* gt    = nullptr;
    const int*   faces = nullptr;
    for (int i = 0; i < n_in; i++) {
        if (in_sizes[i] == NV * 3)      verts = (const float*)d_in[i];
        else if (in_sizes[i] == HW)     gt    = (const float*)d_in[i];
        else if (in_sizes[i] == NF * 3) faces = (const int*)d_in[i];
    }
    float* out = (float*)d_out;
    (void)out_size;
    silhouette_kernel<<<NBLK, NT>>>(verts, faces, gt, out);
}

// round 10
// speedup vs baseline: 1.0473x; 1.0473x over previous
#include <cuda_runtime.h>
#include <cuda_bf16.h>

#define HIMG 240
#define WIMG 135
#define HW   (HIMG * WIMG)
#define NF   1000
#define NV   600
#define INV_SIGMA 1.0e4f
#define BLURF 9.210240366975849e-4f
#define BAND  0.05f

#define NT     256                 // 8 warps
#define SPLIT  4                   // row-slices per face
#define NRAST  (NF * SPLIT)        // 4000 raster blocks
#define NFIN   127                 // finalize blocks: 127*256 = 32512 >= HW
#define NBLK   (NRAST + NFIN)

struct __align__(16) FD {
    float ax, ay, bx, by, cx, cy;
    float e0x, e0y, e1x, e1y, e2x, e2y;
    float rl0, rl1, rl2, rd0, rd1, rd2;
    int x0, x1, y0, y1;
    int skip;
};

__device__ float    g_sum[HW];    // zero at load; finalize self-cleans
__device__ float    g_flag[HW];   // zero at load; finalize self-cleans
__device__ unsigned g_done = 0;   // raster completions; reset by last fin block
__device__ unsigned g_fin  = 0;   // finalize blocks past the gate; self-resets

__global__ void __launch_bounds__(NT)
silhouette_kernel(const float* __restrict__ verts,
                  const int*   __restrict__ faces,
                  const float* __restrict__ gt,
                  float* __restrict__ out /* [0]=loss, [1..]=sil */) {
    const int tid  = threadIdx.x;
    const int lane = tid & 31;
    const int warp = tid >> 5;                  // 0..7
    const int bid  = blockIdx.x;

    // ======================= RASTER ROLE ==================================
    if (bid < NRAST) {
        __shared__ FD sfd;
        const int f  = bid >> 2;                // SPLIT == 4
        const int sl = bid & 3;

        if (bid == 0 && tid == 0) out[0] = 0.0f;

        // ---- setup: warp 0 only, broadcast via smem ----
        if (warp == 0) {
            int idx[3];
            idx[0] = faces[3 * f + 0];
            idx[1] = faces[3 * f + 1];
            idx[2] = faces[3 * f + 2];

            float Px[3], Py[3], zs[3];
#pragma unroll
            for (int k = 0; k < 3; k++) {
                float x = verts[3 * idx[k] + 0];
                float y = verts[3 * idx[k] + 1];
                float z = verts[3 * idx[k] + 2];
                float vx = -x, vy = -y, vz = z;     // R = diag(-1,-1,1)
                zs[k] = vz;
                float zz = fmaxf(vz, 1e-6f);
                Px[k] = (__fdividef(1000.0f * vx, zz) + 512.0f) * ((float)WIMG / 1024.0f);
                Py[k] = (__fdividef(1000.0f * vy, zz) + 512.0f) * ((float)HIMG / 1024.0f);
            }
            float tz = (zs[0] + zs[1] + zs[2]) * (1.0f / 3.0f);

            FD fd;
            fd.ax = Px[0]; fd.ay = Py[0];
            fd.bx = Px[1]; fd.by = Py[1];
            fd.cx = Px[2]; fd.cy = Py[2];
            fd.e0x = fd.bx - fd.ax; fd.e0y = fd.by - fd.ay;
            fd.e1x = fd.cx - fd.bx; fd.e1y = fd.cy - fd.by;
            fd.e2x = fd.ax - fd.cx; fd.e2y = fd.ay - fd.cy;
            float l0 = fd.e0x * fd.e0x + fd.e0y * fd.e0y + 1e-12f;
            float l1 = fd.e1x * fd.e1x + fd.e1y * fd.e1y + 1e-12f;
            float l2 = fd.e2x * fd.e2x + fd.e2y * fd.e2y + 1e-12f;
            fd.rl0 = rsqrtf(l0); fd.rl1 = rsqrtf(l1); fd.rl2 = rsqrtf(l2);
            fd.rd0 = fd.rl0 * fd.rl0;
            fd.rd1 = fd.rl1 * fd.rl1;
            fd.rd2 = fd.rl2 * fd.rl2;

            fd.skip = !(tz > 1e-6f);
            if (!fd.skip) {
                float minx = fminf(fd.ax, fminf(fd.bx, fd.cx));
                float maxx = fmaxf(fd.ax, fmaxf(fd.bx, fd.cx));
                float miny = fminf(fd.ay, fminf(fd.by, fd.cy));
                float maxy = fmaxf(fd.ay, fmaxf(fd.by, fd.cy));
                fd.x0 = max(0, (int)floorf(minx) - 1);
                fd.x1 = min(WIMG - 1, (int)ceilf(maxx));
                fd.y0 = max(0, (int)floorf(miny) - 1);
                fd.y1 = min(HIMG - 1, (int)ceilf(maxy));
                // point-degenerate: reference marks every pixel inside
                if (fd.e0x == 0.0f && fd.e0y == 0.0f &&
                    fd.e1x == 0.0f && fd.e1y == 0.0f) {
                    fd.x0 = 0; fd.x1 = WIMG - 1; fd.y0 = 0; fd.y1 = HIMG - 1;
                }
            } else {
                fd.x0 = 1; fd.x1 = 0; fd.y0 = 1; fd.y1 = 0;
            }
            if (lane == 0) sfd = fd;
        }
        __syncthreads();
        const FD fd = sfd;

        if (!fd.skip) {
            const int nrows = fd.y1 - fd.y0 + 1;
            for (int r = sl + warp * SPLIT; r < nrows; r += 8 * SPLIT) {
                int   iy  = fd.y0 + r;
                float py  = (float)iy + 0.5f;
                int   row = iy * WIMG;
                for (int ix = fd.x0 + lane; ix <= fd.x1; ix += 32) {
                    float px = (float)ix + 0.5f;

                    float apx0 = px - fd.ax, apy0 = py - fd.ay;
                    float apx1 = px - fd.bx, apy1 = py - fd.by;
                    float apx2 = px - fd.cx, apy2 = py - fd.cy;

                    float c0 = fd.e0x * apy0 - fd.e0y * apx0;
                    float c1 = fd.e1x * apy1 - fd.e1y * apx1;
                    float c2 = fd.e2x * apy2 - fd.e2y * apx2;
                    bool inside = (c0 >= 0.0f && c1 >= 0.0f && c2 >= 0.0f) ||
                                  (c0 <= 0.0f && c1 <= 0.0f && c2 <= 0.0f);

                    float dl = fminf(fabsf(c0) * fd.rl0,
                               fminf(fabsf(c1) * fd.rl1, fabsf(c2) * fd.rl2));

                    if (inside && dl > BAND) {
                        // log contribution <= -25: alpha saturates -> flag
                        g_flag[row + ix] = 1.0f;        // idempotent store
                    } else if (inside || dl <= BAND) {
                        float t0 = fminf(fmaxf((apx0 * fd.e0x + apy0 * fd.e0y) * fd.rd0, 0.0f), 1.0f);
                        float rx = apx0 - t0 * fd.e0x;
                        float ry = apy0 - t0 * fd.e0y;
                        float d2min = rx * rx + ry * ry;

                        float t1 = fminf(fmaxf((apx1 * fd.e1x + apy1 * fd.e1y) * fd.rd1, 0.0f), 1.0f);
                        rx = apx1 - t1 * fd.e1x;
                        ry = apy1 - t1 * fd.e1y;
                        d2min = fminf(d2min, rx * rx + ry * ry);

                        float t2 = fminf(fmaxf((apx2 * fd.e2x + apy2 * fd.e2y) * fd.rd2, 0.0f), 1.0f);
                        rx = apx2 - t2 * fd.e2x;
                        ry = apy2 - t2 * fd.e2y;
                        d2min = fminf(d2min, rx * rx + ry * ry);

                        if (inside || d2min <= BLURF) {
                            float u = (inside ? d2min : -d2min) * INV_SIGMA;
                            // log1p(-sigmoid(u)) == -softplus(u)
                            float sp = (u > 15.0f) ? u : log1pf(__expf(u));
                            if (sp != 0.0f) atomicAdd(&g_sum[row + ix], -sp);
                        }
                    }
                    // outside & dl > BAND -> d2 > BLURF -> reference-invalid
                }
            }
        }

        // signal completion (skipped faces too) — one RED per block
        __syncthreads();
        __threadfence();
        if (tid == 0) atomicAdd(&g_done, 1u);
        return;
    }

    // ======================= FINALIZE ROLE ================================
    {
        const int fb = bid - NRAST;               // 0..NFIN-1

        // gate: READ-ONLY polling (no RMW -> no L2 atomic-unit contention
        // with the raster completion REDs). 256ns backoff.
        if (tid == 0) {
            while (*(volatile unsigned*)&g_done < (unsigned)NRAST)
                __nanosleep(256);
        }
        __syncthreads();
        __threadfence();                           // acquire raster writes

        int i = fb * NT + tid;
        float local = 0.0f;
        if (i < HW) {
            float s  = g_sum[i];
            float fl = g_flag[i];
            g_sum[i]  = 0.0f;                      // self-clean for replay
            g_flag[i] = 0.0f;
            float alpha = (fl != 0.0f) ? 1.0f : (1.0f - expf(s));
            out[1 + i] = alpha;
            local = fabsf(alpha - gt[i]);
        }
#pragma unroll
        for (int o = 16; o > 0; o >>= 1)
            local += __shfl_down_sync(0xffffffffu, local, o);

        __shared__ float ws[8];
        if (lane == 0) ws[warp] = local;
        __syncthreads();
        if (warp == 0) {
            float v = (lane < 8) ? ws[lane] : 0.0f;
#pragma unroll
            for (int o = 4; o > 0; o >>= 1)
                v += __shfl_down_sync(0xffu, v, o);
            if (lane == 0)
                atomicAdd(out, v * (1.0f / (float)HW));
        }

        // counter hygiene: last finalize block past the gate resets both.
        // All peers already passed the gate, so no spinner can be stranded.
        if (tid == 0) {
            unsigned old = atomicAdd(&g_fin, 1u);
            if (old == NFIN - 1) {
                g_fin  = 0;
                g_done = 0;
                __threadfence();
            }
        }
    }
}

extern "C" void kernel_launch(void* const* d_in, const int* in_sizes, int n_in,
                              void* d_out, int out_size) {
    const float* verts = nullptr;
    const float* gt    = nullptr;
    const int*   faces = nullptr;
    for (int i = 0; i < n_in; i++) {
        if (in_sizes[i] == NV * 3)      verts = (const float*)d_in[i];
        else if (in_sizes[i] == HW)     gt    = (const float*)d_in[i];
        else if (in_sizes[i] == NF * 3) faces = (const int*)d_in[i];
    }
    float* out = (float*)d_out;
    (void)out_size;
    silhouette_kernel<<<NBLK, NT>>>(verts, faces, gt, out);
}